// round 9
// baseline (speedup 1.0000x reference)
#include <cuda_runtime.h>
#include <cuda_fp16.h>
#include <cstdint>

#define SCALE 0.05103103630798288f   // 384^-0.5
#define NST 3
#define STG_QK 20480                  // A 10240 + B 10240 (K-major)
#define STG_T  18944                  // A 10240 + B 8704  (B MN-major, 272B stride)
#define SMEM_QK (NST * STG_QK)        // 61440
#define SMEM_T  (NST * STG_T)         // 56832

__device__ __half g_Xh[16 * 2048 * 384];
__device__ __half g_Wh[3 * 384 * 384];           // W[k][n] row-major fp16, Wq pre-scaled
__device__ __half g_Qh[16 * 2048 * 384];
__device__ __half g_Kh[16 * 2048 * 384];
__device__ __half g_Vh[16 * 2048 * 384];
__device__ __half g_Pt[16ll * 2048 * 2048];      // P~ = exp(S - m_tile), fp16
__device__ float  g_mt[16 * 16 * 16 * 128];
__device__ float  g_lt[16 * 16 * 16 * 128];
__device__ float  g_g [16 * 16 * 16 * 128];      // fold factor exp(m_t-M)/l

__device__ __forceinline__ uint32_t smem_u32(const void* p) {
    uint32_t a;
    asm("{ .reg .u64 t; cvta.to.shared.u64 t, %1; cvt.u32.u64 %0, t; }" : "=r"(a) : "l"(p));
    return a;
}
__device__ __forceinline__ void cpa16(uint32_t dst, const void* src) {
    asm volatile("cp.async.cg.shared.global [%0], [%1], 16;" :: "r"(dst), "l"(src));
}
#define CP_COMMIT() asm volatile("cp.async.commit_group;" ::: "memory")
#define CP_WAIT1()  asm volatile("cp.async.wait_group 1;" ::: "memory")

__device__ __forceinline__ void ldsm4(uint32_t addr, uint32_t* r) {
    asm volatile("ldmatrix.sync.aligned.m8n8.x4.shared.b16 {%0,%1,%2,%3}, [%4];"
        : "=r"(r[0]), "=r"(r[1]), "=r"(r[2]), "=r"(r[3]) : "r"(addr));
}
__device__ __forceinline__ void ldsm4t(uint32_t addr, uint32_t* r) {
    asm volatile("ldmatrix.sync.aligned.m8n8.x4.trans.shared.b16 {%0,%1,%2,%3}, [%4];"
        : "=r"(r[0]), "=r"(r[1]), "=r"(r[2]), "=r"(r[3]) : "r"(addr));
}
__device__ __forceinline__ void mmah(float* c, const uint32_t* a, const uint32_t* b) {
    asm volatile("mma.sync.aligned.m16n8k16.row.col.f32.f16.f16.f32 "
        "{%0,%1,%2,%3}, {%4,%5,%6,%7}, {%8,%9}, {%0,%1,%2,%3};"
        : "+f"(c[0]), "+f"(c[1]), "+f"(c[2]), "+f"(c[3])
        : "r"(a[0]), "r"(a[1]), "r"(a[2]), "r"(a[3]), "r"(b[0]), "r"(b[1]));
}

#define ACC_DECL()                                   \
    float acc[2][8][4];                              \
    _Pragma("unroll") for (int i_ = 0; i_ < 2; i_++) \
    _Pragma("unroll") for (int j_ = 0; j_ < 8; j_++) \
    _Pragma("unroll") for (int q_ = 0; q_ < 4; q_++) acc[i_][j_][q_] = 0.f;

#define AOFF(wm, lane) ((uint32_t)(((wm) * 32 + ((lane) & 15)) * 80 + ((lane) >> 4) * 16))
#define BOFF(wn, lane) ((uint32_t)(((wn) * 64 + (((lane) >> 4) & 1) * 8 + ((lane) & 7)) * 80 + \
                                   (((lane) >> 3) & 1) * 16))
#define BOFFT(wn, lane) ((uint32_t)(((((lane) >> 3) & 1) * 8 + ((lane) & 7)) * 272 + \
                                    ((wn) * 64 + (((lane) >> 4) & 1) * 8) * 2))

// K-major 1-pass chunk: A@0 (80B stride), B@10240 (80B stride)
__device__ __forceinline__ void chunk1(uint32_t sbase, uint32_t aOff, uint32_t bOff,
                                       float acc[2][8][4]) {
#pragma unroll
    for (int ks = 0; ks < 2; ks++) {
        uint32_t a[2][4], b[8][2];
#pragma unroll
        for (int mf = 0; mf < 2; mf++) ldsm4(sbase + aOff + mf * 1280 + ks * 32, a[mf]);
#pragma unroll
        for (int n2 = 0; n2 < 4; n2++) {
            uint32_t r[4];
            ldsm4(sbase + 10240 + bOff + n2 * 1280 + ks * 32, r);
            b[n2 * 2][0] = r[0]; b[n2 * 2][1] = r[1];
            b[n2 * 2 + 1][0] = r[2]; b[n2 * 2 + 1][1] = r[3];
        }
#pragma unroll
        for (int mf = 0; mf < 2; mf++)
#pragma unroll
            for (int nf = 0; nf < 8; nf++) mmah(acc[mf][nf], a[mf], b[nf]);
    }
}

// MN-major-B 1-pass chunk: A@0, B@10240 (32 rows x 272B), ldsm.trans.
// If SCALED, multiply A fragments by per-row g factors (ga=rows r, gb=rows r+8).
template <bool SCALED>
__device__ __forceinline__ void chunk1t(uint32_t sbase, uint32_t aOff, uint32_t bOff,
                                        float acc[2][8][4],
                                        const __half2* ga, const __half2* gb) {
#pragma unroll
    for (int ks = 0; ks < 2; ks++) {
        uint32_t a[2][4], b[8][2];
#pragma unroll
        for (int mf = 0; mf < 2; mf++) {
            ldsm4(sbase + aOff + mf * 1280 + ks * 32, a[mf]);
            if (SCALED) {
                __half2* ap = reinterpret_cast<__half2*>(a[mf]);
                ap[0] = __hmul2(ap[0], ga[mf]);
                ap[2] = __hmul2(ap[2], ga[mf]);
                ap[1] = __hmul2(ap[1], gb[mf]);
                ap[3] = __hmul2(ap[3], gb[mf]);
            }
        }
#pragma unroll
        for (int n2 = 0; n2 < 4; n2++) {
            uint32_t r[4];
            ldsm4t(sbase + 10240 + bOff + (uint32_t)(ks * 16 * 272 + n2 * 32), r);
            b[n2 * 2][0] = r[0]; b[n2 * 2][1] = r[1];
            b[n2 * 2 + 1][0] = r[2]; b[n2 * 2 + 1][1] = r[3];
        }
#pragma unroll
        for (int mf = 0; mf < 2; mf++)
#pragma unroll
            for (int nf = 0; nf < 8; nf++) mmah(acc[mf][nf], a[mf], b[nf]);
    }
}

// ---------------- cvt: inputs fp32 -> fp16 (SCALE folded into Wq) ----------------
struct __align__(8) hpair { __half2 a, b; };
__device__ __forceinline__ hpair to_h(float4 v) {
    hpair r; r.a = __floats2half2_rn(v.x, v.y); r.b = __floats2half2_rn(v.z, v.w); return r;
}
__global__ void cvtx_kernel(const float* __restrict__ X) {
    size_t i = ((size_t)blockIdx.x * 256 + threadIdx.x) * 4;
    *(hpair*)&g_Xh[i] = to_h(*(const float4*)(X + i));
}
__global__ void cvtw_kernel(const float* __restrict__ Wq, const float* __restrict__ Wk,
                            const float* __restrict__ Wv) {
    int i = (blockIdx.x * 256 + threadIdx.x) * 4;
    int z = i / 147456, r = i - z * 147456;
    const float* W = (z == 0) ? Wq : ((z == 1) ? Wk : Wv);
    float4 v = *(const float4*)(W + r);
    float s = (z == 0) ? SCALE : 1.f;
    v.x *= s; v.y *= s; v.z *= s; v.w *= s;
    *(hpair*)&g_Wh[i] = to_h(v);
}

// ---------------- proj: Xh(fp16) . Wh(fp16), cp.async 3-stage ----------------
__global__ void __launch_bounds__(256, 3) proj_kernel() {
    extern __shared__ char smem[];
    int tid = threadIdx.x, lane = tid & 31, wid = tid >> 5, wm = wid & 3, wn = wid >> 2;
    uint32_t sb = smem_u32(smem);
    int nt = blockIdx.x * 128, mt = blockIdx.y * 128, z = blockIdx.z;
    const __half* gA = g_Xh + (size_t)mt * 384;
    const __half* gW = g_Wh + (size_t)z * 147456 + nt;
    ACC_DECL();

    int rr = tid >> 2, cc = (tid & 3) * 8;
    int r2 = tid >> 4, c2 = (tid & 15) * 8;
    auto issue = [&](int c, int s) {
        uint32_t buf = sb + (uint32_t)(s * STG_T);
#pragma unroll
        for (int i = 0; i < 2; i++) {
            int rri = rr + i * 64, r2i = r2 + i * 16;
            cpa16(buf + rri * 80 + cc * 2, gA + (size_t)rri * 384 + c * 32 + cc);
            cpa16(buf + 10240 + r2i * 272 + c2 * 2, gW + (size_t)(c * 32 + r2i) * 384 + c2);
        }
        CP_COMMIT();
    };
    uint32_t aOff = AOFF(wm, lane), bOff = BOFFT(wn, lane);
    issue(0, 0); issue(1, 1);
    for (int c = 0; c < 12; c++) {
        CP_WAIT1();
        __syncthreads();
        if (c + 2 < 12) issue(c + 2, (c + 2) % NST); else CP_COMMIT();
        chunk1t<false>(sb + (uint32_t)((c % NST) * STG_T), aOff, bOff, acc, 0, 0);
    }

    __half* Yh = (z == 0) ? g_Qh : ((z == 1) ? g_Kh : g_Vh);
#pragma unroll
    for (int mf = 0; mf < 2; mf++)
#pragma unroll
        for (int h = 0; h < 2; h++) {
            int row = mt + wm * 32 + mf * 16 + (lane >> 2) + h * 8;
#pragma unroll
            for (int nf = 0; nf < 8; nf++) {
                int col = nt + wn * 64 + nf * 8 + (lane & 3) * 2;
                *(__half2*)&Yh[(size_t)row * 384 + col] =
                    __floats2half2_rn(acc[mf][nf][h * 2], acc[mf][nf][h * 2 + 1]);
            }
        }
}

// ---------------- qk: cp.async 3-stage + fused local softmax ----------------
__global__ void __launch_bounds__(256, 3) qk_kernel() {
    extern __shared__ char smem[];
    int tid = threadIdx.x, lane = tid & 31, wid = tid >> 5, wm = wid & 3, wn = wid >> 2;
    uint32_t sb = smem_u32(smem);
    int b = blockIdx.y, r_ = blockIdx.x, qt = 0;
    while (r_ > qt) { r_ -= qt + 1; qt++; }
    int kt = r_;
    const __half* gQ = g_Qh + ((size_t)b * 2048 + qt * 128) * 384;
    const __half* gK = g_Kh + ((size_t)b * 2048 + kt * 128) * 384;
    ACC_DECL();

    int rr = tid >> 2, cc = (tid & 3) * 8;
    auto issue = [&](int c, int s) {
        uint32_t buf = sb + (uint32_t)(s * STG_QK);
#pragma unroll
        for (int i = 0; i < 2; i++) {
            int rri = rr + i * 64;
            uint32_t o = rri * 80 + cc * 2;
            size_t go = (size_t)rri * 384 + c * 32 + cc;
            cpa16(buf + o, gQ + go);
            cpa16(buf + 10240 + o, gK + go);
        }
        CP_COMMIT();
    };
    uint32_t aOff = AOFF(wm, lane), bOff = BOFF(wn, lane);
    issue(0, 0); issue(1, 1);
    for (int c = 0; c < 12; c++) {
        CP_WAIT1();
        __syncthreads();
        if (c + 2 < 12) issue(c + 2, (c + 2) % NST); else CP_COMMIT();
        chunk1(sb + (uint32_t)((c % NST) * STG_QK), aOff, bOff, acc);
    }

    // ---- fused epilogue: mask, local max, exp, row sums, P~ store ----
    float* sR = (float*)smem;            // [2][128] (stage-0 A region, free by now)
    float pm[2][2] = {{-1e30f, -1e30f}, {-1e30f, -1e30f}};
#pragma unroll
    for (int mf = 0; mf < 2; mf++)
#pragma unroll
        for (int nf = 0; nf < 8; nf++)
#pragma unroll
            for (int q = 0; q < 4; q++) {
                int h = q >> 1;
                int qg = qt * 128 + wm * 32 + mf * 16 + (lane >> 2) + h * 8;
                int kg = kt * 128 + wn * 64 + nf * 8 + (lane & 3) * 2 + (q & 1);
                if (kg > qg) acc[mf][nf][q] = -1e30f;
                pm[mf][h] = fmaxf(pm[mf][h], acc[mf][nf][q]);
            }
#pragma unroll
    for (int mf = 0; mf < 2; mf++)
#pragma unroll
        for (int h = 0; h < 2; h++) {
            pm[mf][h] = fmaxf(pm[mf][h], __shfl_xor_sync(~0u, pm[mf][h], 1));
            pm[mf][h] = fmaxf(pm[mf][h], __shfl_xor_sync(~0u, pm[mf][h], 2));
        }
    int rl[2][2];
#pragma unroll
    for (int mf = 0; mf < 2; mf++)
#pragma unroll
        for (int h = 0; h < 2; h++)
            rl[mf][h] = wm * 32 + mf * 16 + (lane >> 2) + h * 8;
    __syncthreads();
    if ((lane & 3) == 0)
#pragma unroll
        for (int mf = 0; mf < 2; mf++)
#pragma unroll
            for (int h = 0; h < 2; h++) sR[wn * 128 + rl[mf][h]] = pm[mf][h];
    __syncthreads();
    float mrow[2][2], ps[2][2] = {{0.f, 0.f}, {0.f, 0.f}};
#pragma unroll
    for (int mf = 0; mf < 2; mf++)
#pragma unroll
        for (int h = 0; h < 2; h++) mrow[mf][h] = fmaxf(sR[rl[mf][h]], sR[128 + rl[mf][h]]);
#pragma unroll
    for (int mf = 0; mf < 2; mf++)
#pragma unroll
        for (int nf = 0; nf < 8; nf++)
#pragma unroll
            for (int q = 0; q < 4; q++) {
                int h = q >> 1;
                float p = __expf(acc[mf][nf][q] - mrow[mf][h]);
                acc[mf][nf][q] = p;
                ps[mf][h] += p;
            }
#pragma unroll
    for (int mf = 0; mf < 2; mf++)
#pragma unroll
        for (int h = 0; h < 2; h++) {
            ps[mf][h] += __shfl_xor_sync(~0u, ps[mf][h], 1);
            ps[mf][h] += __shfl_xor_sync(~0u, ps[mf][h], 2);
        }
    __syncthreads();
    if ((lane & 3) == 0)
#pragma unroll
        for (int mf = 0; mf < 2; mf++)
#pragma unroll
            for (int h = 0; h < 2; h++) sR[wn * 128 + rl[mf][h]] = ps[mf][h];
    __syncthreads();
    size_t statb = ((size_t)(b * 16 + qt) * 16 + kt) * 128;
    if (wn == 0 && (lane & 3) == 0)
#pragma unroll
        for (int mf = 0; mf < 2; mf++)
#pragma unroll
            for (int h = 0; h < 2; h++) {
                g_mt[statb + rl[mf][h]] = mrow[mf][h];
                g_lt[statb + rl[mf][h]] = sR[rl[mf][h]] + sR[128 + rl[mf][h]];
            }
    __half* Prow = g_Pt + ((size_t)b * 2048 + qt * 128) * 2048 + (size_t)kt * 128;
#pragma unroll
    for (int mf = 0; mf < 2; mf++)
#pragma unroll
        for (int h = 0; h < 2; h++) {
#pragma unroll
            for (int nf = 0; nf < 8; nf++) {
                int col = wn * 64 + nf * 8 + (lane & 3) * 2;
                *(__half2*)&Prow[(size_t)rl[mf][h] * 2048 + col] =
                    __floats2half2_rn(acc[mf][nf][h * 2], acc[mf][nf][h * 2 + 1]);
            }
        }
}

// ---------------- norm: fold M and 1/l into per-tile row factors ----------------
__global__ void __launch_bounds__(128) norm_kernel() {
    int bq = blockIdx.x;                // b*16 + qt
    int qt = bq & 15, row = threadIdx.x;
    int ntl = qt + 1;
    size_t base = (size_t)bq * 16 * 128 + row;
    float m = -1e30f;
    for (int t = 0; t < ntl; t++) m = fmaxf(m, g_mt[base + t * 128]);
    float l = 0.f;
    for (int t = 0; t < ntl; t++) l += __expf(g_mt[base + t * 128] - m) * g_lt[base + t * 128];
    float inv = 1.f / l;
    for (int t = 0; t < ntl; t++) g_g[base + t * 128] = __expf(g_mt[base + t * 128] - m) * inv;
}

// ---------------- pv: cp.async 3-stage; g applied to A fragments post-ldsm ----------------
__global__ void __launch_bounds__(256, 3) pv_kernel(float* __restrict__ out) {
    extern __shared__ char smem[];
    int tid = threadIdx.x, lane = tid & 31, wid = tid >> 5, wm = wid & 3, wn = wid >> 2;
    uint32_t sb = smem_u32(smem);
    int nt = blockIdx.x * 128, qt = 15 - (int)blockIdx.y, b = blockIdx.z;
    int nch = (qt + 1) * 4;
    const __half* Pb = g_Pt + ((size_t)b * 2048 + qt * 128) * 2048;
    const __half* Vh = g_Vh + (size_t)b * 2048 * 384 + nt;
    const size_t statb = (size_t)(b * 16 + qt) * 16 * 128;
    ACC_DECL();

    int rr = tid >> 2, cc = (tid & 3) * 8;
    int r2 = tid >> 4, c2 = (tid & 15) * 8;
    auto issue = [&](int c, int s) {
        uint32_t buf = sb + (uint32_t)(s * STG_T);
#pragma unroll
        for (int i = 0; i < 2; i++) {
            int rri = rr + i * 64, r2i = r2 + i * 16;
            cpa16(buf + rri * 80 + cc * 2, Pb + (size_t)rri * 2048 + c * 32 + cc);
            cpa16(buf + 10240 + r2i * 272 + c2 * 2, Vh + (size_t)(c * 32 + r2i) * 384 + c2);
        }
        CP_COMMIT();
    };
    uint32_t aOff = AOFF(wm, lane), bOff = BOFFT(wn, lane);
    issue(0, 0); issue(1, 1);

    __half2 ga[2], gb[2];
    int rbase = wm * 32 + (lane >> 2);
    for (int c = 0; c < nch; c++) {
        if ((c & 3) == 0) {
            const float* gp = g_g + statb + (size_t)(c >> 2) * 128;
#pragma unroll
            for (int mf = 0; mf < 2; mf++) {
                ga[mf] = __float2half2_rn(gp[rbase + mf * 16]);
                gb[mf] = __float2half2_rn(gp[rbase + mf * 16 + 8]);
            }
        }
        CP_WAIT1();
        __syncthreads();
        if (c + 2 < nch) issue(c + 2, (c + 2) % NST); else CP_COMMIT();
        chunk1t<true>(sb + (uint32_t)((c % NST) * STG_T), aOff, bOff, acc, ga, gb);
    }

    float* Y = out + ((size_t)b * 2048 + qt * 128) * 384 + nt;
#pragma unroll
    for (int mf = 0; mf < 2; mf++)
#pragma unroll
        for (int h = 0; h < 2; h++) {
            int row = wm * 32 + mf * 16 + (lane >> 2) + h * 8;
#pragma unroll
            for (int nf = 0; nf < 8; nf++) {
                float2 v = make_float2(acc[mf][nf][h * 2], acc[mf][nf][h * 2 + 1]);
                *(float2*)&Y[(size_t)row * 384 + wn * 64 + nf * 8 + (lane & 3) * 2] = v;
            }
        }
}

extern "C" void kernel_launch(void* const* d_in, const int* in_sizes, int n_in,
                              void* d_out, int out_size) {
    const float* x  = (const float*)d_in[0];
    const float* Wq = (const float*)d_in[1];
    const float* Wk = (const float*)d_in[2];
    const float* Wv = (const float*)d_in[3];
    float* out = (float*)d_out;
    (void)in_sizes; (void)n_in; (void)out_size;

    cudaFuncSetAttribute(proj_kernel, cudaFuncAttributeMaxDynamicSharedMemorySize, SMEM_T);
    cudaFuncSetAttribute(qk_kernel,   cudaFuncAttributeMaxDynamicSharedMemorySize, SMEM_QK);
    cudaFuncSetAttribute(pv_kernel,   cudaFuncAttributeMaxDynamicSharedMemorySize, SMEM_T);

    cvtx_kernel<<<12288, 256>>>(x);
    cvtw_kernel<<<432, 256>>>(Wq, Wk, Wv);
    proj_kernel<<<dim3(3, 256, 3), 256, SMEM_T>>>();
    qk_kernel<<<dim3(136, 16), 256, SMEM_QK>>>();
    norm_kernel<<<256, 128>>>();
    pv_kernel<<<dim3(3, 16, 16), 256, SMEM_T>>>(out);
}

// round 10
// speedup vs baseline: 1.4390x; 1.4390x over previous
#include <cuda_runtime.h>
#include <cuda_fp16.h>
#include <cstdint>

#define SCALE 0.05103103630798288f   // 384^-0.5
#define SMEM_GEMM 40960               // 2 buf * (A 10240 + B 10240)  K-major B
#define SMEM_T    37888               // 2 buf * (A 10240 + B 8704)   MN-major B
#define STG_T     18944

__device__ __half g_Wh[3 * 384 * 384];           // W[k][n] fp16, Wq pre-scaled
__device__ __half g_Qh[16 * 2048 * 384];
__device__ __half g_Kh[16 * 2048 * 384];
__device__ __half g_Vh[16 * 2048 * 384];
__device__ __half g_Pt[16ll * 2048 * 2048];      // P~ = exp(S - m_tile), fp16
__device__ float  g_mt[16 * 16 * 16 * 128];
__device__ float  g_lt[16 * 16 * 16 * 128];
__device__ float  g_g [16 * 16 * 16 * 128];      // fold factor exp(m_t-M)/l

__device__ __forceinline__ uint32_t smem_u32(const void* p) {
    uint32_t a;
    asm("{ .reg .u64 t; cvta.to.shared.u64 t, %1; cvt.u32.u64 %0, t; }" : "=r"(a) : "l"(p));
    return a;
}
__device__ __forceinline__ void ldsm4(uint32_t addr, uint32_t* r) {
    asm volatile("ldmatrix.sync.aligned.m8n8.x4.shared.b16 {%0,%1,%2,%3}, [%4];"
        : "=r"(r[0]), "=r"(r[1]), "=r"(r[2]), "=r"(r[3]) : "r"(addr));
}
__device__ __forceinline__ void ldsm4t(uint32_t addr, uint32_t* r) {
    asm volatile("ldmatrix.sync.aligned.m8n8.x4.trans.shared.b16 {%0,%1,%2,%3}, [%4];"
        : "=r"(r[0]), "=r"(r[1]), "=r"(r[2]), "=r"(r[3]) : "r"(addr));
}
__device__ __forceinline__ void mmah(float* c, const uint32_t* a, const uint32_t* b) {
    asm volatile("mma.sync.aligned.m16n8k16.row.col.f32.f16.f16.f32 "
        "{%0,%1,%2,%3}, {%4,%5,%6,%7}, {%8,%9}, {%0,%1,%2,%3};"
        : "+f"(c[0]), "+f"(c[1]), "+f"(c[2]), "+f"(c[3])
        : "r"(a[0]), "r"(a[1]), "r"(a[2]), "r"(a[3]), "r"(b[0]), "r"(b[1]));
}

#define ACC_DECL()                                   \
    float acc[2][8][4];                              \
    _Pragma("unroll") for (int i_ = 0; i_ < 2; i_++) \
    _Pragma("unroll") for (int j_ = 0; j_ < 8; j_++) \
    _Pragma("unroll") for (int q_ = 0; q_ < 4; q_++) acc[i_][j_][q_] = 0.f;

#define AOFF(wm, lane) ((uint32_t)(((wm) * 32 + ((lane) & 15)) * 80 + ((lane) >> 4) * 16))
#define BOFF(wn, lane) ((uint32_t)(((wn) * 64 + (((lane) >> 4) & 1) * 8 + ((lane) & 7)) * 80 + \
                                   (((lane) >> 3) & 1) * 16))
#define BOFFT(wn, lane) ((uint32_t)(((((lane) >> 3) & 1) * 8 + ((lane) & 7)) * 272 + \
                                    ((wn) * 64 + (((lane) >> 4) & 1) * 8) * 2))

// K-major 1-pass chunk: A@0 (80B stride), B@10240 (80B stride)
__device__ __forceinline__ void chunk1(uint32_t sbase, uint32_t aOff, uint32_t bOff,
                                       float acc[2][8][4]) {
#pragma unroll
    for (int ks = 0; ks < 2; ks++) {
        uint32_t a[2][4], b[8][2];
#pragma unroll
        for (int mf = 0; mf < 2; mf++) ldsm4(sbase + aOff + mf * 1280 + ks * 32, a[mf]);
#pragma unroll
        for (int n2 = 0; n2 < 4; n2++) {
            uint32_t r[4];
            ldsm4(sbase + 10240 + bOff + n2 * 1280 + ks * 32, r);
            b[n2 * 2][0] = r[0]; b[n2 * 2][1] = r[1];
            b[n2 * 2 + 1][0] = r[2]; b[n2 * 2 + 1][1] = r[3];
        }
#pragma unroll
        for (int mf = 0; mf < 2; mf++)
#pragma unroll
            for (int nf = 0; nf < 8; nf++) mmah(acc[mf][nf], a[mf], b[nf]);
    }
}

// MN-major-B 1-pass chunk: A@0, B@10240 (32 rows x 272B), ldsm.trans.
// If SCALED, multiply A fragments by per-row g factors (ga=rows r, gb=rows r+8).
template <bool SCALED>
__device__ __forceinline__ void chunk1t(uint32_t sbase, uint32_t aOff, uint32_t bOff,
                                        float acc[2][8][4],
                                        const __half2* ga, const __half2* gb) {
#pragma unroll
    for (int ks = 0; ks < 2; ks++) {
        uint32_t a[2][4], b[8][2];
#pragma unroll
        for (int mf = 0; mf < 2; mf++) {
            ldsm4(sbase + aOff + mf * 1280 + ks * 32, a[mf]);
            if (SCALED) {
                __half2* ap = reinterpret_cast<__half2*>(a[mf]);
                ap[0] = __hmul2(ap[0], ga[mf]);
                ap[2] = __hmul2(ap[2], ga[mf]);
                ap[1] = __hmul2(ap[1], gb[mf]);
                ap[3] = __hmul2(ap[3], gb[mf]);
            }
        }
#pragma unroll
        for (int n2 = 0; n2 < 4; n2++) {
            uint32_t r[4];
            ldsm4t(sbase + 10240 + bOff + (uint32_t)(ks * 16 * 272 + n2 * 32), r);
            b[n2 * 2][0] = r[0]; b[n2 * 2][1] = r[1];
            b[n2 * 2 + 1][0] = r[2]; b[n2 * 2 + 1][1] = r[3];
        }
#pragma unroll
        for (int mf = 0; mf < 2; mf++)
#pragma unroll
            for (int nf = 0; nf < 8; nf++) mmah(acc[mf][nf], a[mf], b[nf]);
    }
}

struct __align__(8) hpair { __half2 a, b; };
__device__ __forceinline__ hpair to_h(float4 v) {
    hpair r; r.a = __floats2half2_rn(v.x, v.y); r.b = __floats2half2_rn(v.z, v.w); return r;
}

// ---------------- cvtw: W fp32 -> fp16 (SCALE folded into Wq) ----------------
__global__ void cvtw_kernel(const float* __restrict__ Wq, const float* __restrict__ Wk,
                            const float* __restrict__ Wv) {
    int i = (blockIdx.x * 256 + threadIdx.x) * 4;
    int z = i / 147456, r = i - z * 147456;
    const float* W = (z == 0) ? Wq : ((z == 1) ? Wk : Wv);
    float4 v = *(const float4*)(W + r);
    float s = (z == 0) ? SCALE : 1.f;
    v.x *= s; v.y *= s; v.z *= s; v.w *= s;
    *(hpair*)&g_Wh[i] = to_h(v);
}

// ---------------- proj: X fp32 (convert in stage) x W fp16, ldg->reg->sts ----------------
__global__ void __launch_bounds__(256, 2) proj_kernel(const float* __restrict__ X) {
    extern __shared__ char smem[];
    int tid = threadIdx.x, lane = tid & 31, wid = tid >> 5, wm = wid & 3, wn = wid >> 2;
    uint32_t sb = smem_u32(smem);
    int nt = blockIdx.x * 128, mt = blockIdx.y * 128, z = blockIdx.z;
    const float*  gA = X + (size_t)mt * 384;
    const __half* gW = g_Wh + (size_t)z * 147456 + nt;   // [k][n] fp16
    ACC_DECL();

    float4 va[4]; uint4 wb[2];
    auto ldg = [&](int c) {
#pragma unroll
        for (int i = 0; i < 4; i++) {
            int lin = tid + 256 * i, row = lin >> 3, c4 = (lin & 7) * 4;
            va[i] = *(const float4*)(gA + (size_t)row * 384 + c * 32 + c4);
        }
#pragma unroll
        for (int i = 0; i < 2; i++) {
            int lin = tid + 256 * i, r2 = lin >> 4, c2 = (lin & 15) * 8;
            wb[i] = *(const uint4*)(gW + (size_t)(c * 32 + r2) * 384 + c2);
        }
    };
    auto stg = [&](char* buf) {
#pragma unroll
        for (int i = 0; i < 4; i++) {
            int lin = tid + 256 * i, row = lin >> 3, c4 = (lin & 7) * 4;
            *(hpair*)(buf + row * 80 + c4 * 2) = to_h(va[i]);
        }
#pragma unroll
        for (int i = 0; i < 2; i++) {
            int lin = tid + 256 * i, r2 = lin >> 4, c2 = (lin & 15) * 8;
            *(uint4*)(buf + 10240 + r2 * 272 + c2 * 2) = wb[i];
        }
    };
    uint32_t aOff = AOFF(wm, lane), bOff = BOFFT(wn, lane);
    ldg(0); stg(smem); __syncthreads();
    for (int c = 0; c < 12; c++) {
        if (c < 11) ldg(c + 1);
        chunk1t<false>(sb + (uint32_t)(c & 1) * STG_T, aOff, bOff, acc, 0, 0);
        if (c < 11) stg(smem + (size_t)((c + 1) & 1) * STG_T);
        __syncthreads();
    }

    __half* Yh = (z == 0) ? g_Qh : ((z == 1) ? g_Kh : g_Vh);
#pragma unroll
    for (int mf = 0; mf < 2; mf++)
#pragma unroll
        for (int h = 0; h < 2; h++) {
            int row = mt + wm * 32 + mf * 16 + (lane >> 2) + h * 8;
#pragma unroll
            for (int nf = 0; nf < 8; nf++) {
                int col = nt + wn * 64 + nf * 8 + (lane & 3) * 2;
                *(__half2*)&Yh[(size_t)row * 384 + col] =
                    __floats2half2_rn(acc[mf][nf][h * 2], acc[mf][nf][h * 2 + 1]);
            }
        }
}

// ---------------- qk: MMA + fused local softmax (round-8 proven) ----------------
__global__ void __launch_bounds__(256, 2) qk_kernel() {
    extern __shared__ char smem[];
    int tid = threadIdx.x, lane = tid & 31, wid = tid >> 5, wm = wid & 3, wn = wid >> 2;
    uint32_t sb = smem_u32(smem);
    int b = blockIdx.y, r_ = blockIdx.x, qt = 0;
    while (r_ > qt) { r_ -= qt + 1; qt++; }
    int kt = r_;
    size_t qb = ((size_t)b * 2048 + qt * 128) * 384;
    size_t kb = ((size_t)b * 2048 + kt * 128) * 384;
    ACC_DECL();

    uint4 rv[4];
    auto ldg = [&](int c) {
#pragma unroll
        for (int i = 0; i < 2; i++) {
            int lin = tid + 256 * i, rr = lin >> 2, cc = (lin & 3) * 8;
            size_t o = (size_t)rr * 384 + c * 32 + cc;
            rv[i * 2 + 0] = *(const uint4*)(g_Qh + qb + o);
            rv[i * 2 + 1] = *(const uint4*)(g_Kh + kb + o);
        }
    };
    auto stg = [&](char* buf) {
#pragma unroll
        for (int i = 0; i < 2; i++) {
            int lin = tid + 256 * i, rr = lin >> 2, cc = (lin & 3) * 8;
            int o = rr * 80 + cc * 2;
            *(uint4*)(buf + o)         = rv[i * 2 + 0];
            *(uint4*)(buf + 10240 + o) = rv[i * 2 + 1];
        }
    };
    uint32_t aOff = AOFF(wm, lane), bOff = BOFF(wn, lane);
    ldg(0); stg(smem); __syncthreads();
    for (int c = 0; c < 12; c++) {
        if (c < 11) ldg(c + 1);
        chunk1(sb + (uint32_t)(c & 1) * 20480u, aOff, bOff, acc);
        if (c < 11) stg(smem + (size_t)((c + 1) & 1) * 20480);
        __syncthreads();
    }

    // ---- fused epilogue: mask, local max, exp, row sums, P~ store ----
    float* sR = (float*)smem;
    float pm[2][2] = {{-1e30f, -1e30f}, {-1e30f, -1e30f}};
#pragma unroll
    for (int mf = 0; mf < 2; mf++)
#pragma unroll
        for (int nf = 0; nf < 8; nf++)
#pragma unroll
            for (int q = 0; q < 4; q++) {
                int h = q >> 1;
                int qg = qt * 128 + wm * 32 + mf * 16 + (lane >> 2) + h * 8;
                int kg = kt * 128 + wn * 64 + nf * 8 + (lane & 3) * 2 + (q & 1);
                if (kg > qg) acc[mf][nf][q] = -1e30f;
                pm[mf][h] = fmaxf(pm[mf][h], acc[mf][nf][q]);
            }
#pragma unroll
    for (int mf = 0; mf < 2; mf++)
#pragma unroll
        for (int h = 0; h < 2; h++) {
            pm[mf][h] = fmaxf(pm[mf][h], __shfl_xor_sync(~0u, pm[mf][h], 1));
            pm[mf][h] = fmaxf(pm[mf][h], __shfl_xor_sync(~0u, pm[mf][h], 2));
        }
    int rl[2][2];
#pragma unroll
    for (int mf = 0; mf < 2; mf++)
#pragma unroll
        for (int h = 0; h < 2; h++)
            rl[mf][h] = wm * 32 + mf * 16 + (lane >> 2) + h * 8;
    if ((lane & 3) == 0)
#pragma unroll
        for (int mf = 0; mf < 2; mf++)
#pragma unroll
            for (int h = 0; h < 2; h++) sR[wn * 128 + rl[mf][h]] = pm[mf][h];
    __syncthreads();
    float mrow[2][2], ps[2][2] = {{0.f, 0.f}, {0.f, 0.f}};
#pragma unroll
    for (int mf = 0; mf < 2; mf++)
#pragma unroll
        for (int h = 0; h < 2; h++) mrow[mf][h] = fmaxf(sR[rl[mf][h]], sR[128 + rl[mf][h]]);
#pragma unroll
    for (int mf = 0; mf < 2; mf++)
#pragma unroll
        for (int nf = 0; nf < 8; nf++)
#pragma unroll
            for (int q = 0; q < 4; q++) {
                int h = q >> 1;
                float p = __expf(acc[mf][nf][q] - mrow[mf][h]);
                acc[mf][nf][q] = p;
                ps[mf][h] += p;
            }
#pragma unroll
    for (int mf = 0; mf < 2; mf++)
#pragma unroll
        for (int h = 0; h < 2; h++) {
            ps[mf][h] += __shfl_xor_sync(~0u, ps[mf][h], 1);
            ps[mf][h] += __shfl_xor_sync(~0u, ps[mf][h], 2);
        }
    __syncthreads();
    if ((lane & 3) == 0)
#pragma unroll
        for (int mf = 0; mf < 2; mf++)
#pragma unroll
            for (int h = 0; h < 2; h++) sR[wn * 128 + rl[mf][h]] = ps[mf][h];
    __syncthreads();
    size_t statb = ((size_t)(b * 16 + qt) * 16 + kt) * 128;
    if (wn == 0 && (lane & 3) == 0)
#pragma unroll
        for (int mf = 0; mf < 2; mf++)
#pragma unroll
            for (int h = 0; h < 2; h++) {
                g_mt[statb + rl[mf][h]] = mrow[mf][h];
                g_lt[statb + rl[mf][h]] = sR[rl[mf][h]] + sR[128 + rl[mf][h]];
            }
    __half* Prow = g_Pt + ((size_t)b * 2048 + qt * 128) * 2048 + (size_t)kt * 128;
#pragma unroll
    for (int mf = 0; mf < 2; mf++)
#pragma unroll
        for (int h = 0; h < 2; h++) {
#pragma unroll
            for (int nf = 0; nf < 8; nf++) {
                int col = wn * 64 + nf * 8 + (lane & 3) * 2;
                *(__half2*)&Prow[(size_t)rl[mf][h] * 2048 + col] =
                    __floats2half2_rn(acc[mf][nf][h * 2], acc[mf][nf][h * 2 + 1]);
            }
        }
}

// ---------------- norm: fold M and 1/l into per-tile row factors ----------------
__global__ void __launch_bounds__(128) norm_kernel() {
    int bq = blockIdx.x;
    int qt = bq & 15, row = threadIdx.x;
    int ntl = qt + 1;
    size_t base = (size_t)bq * 16 * 128 + row;
    float m = -1e30f;
    for (int t = 0; t < ntl; t++) m = fmaxf(m, g_mt[base + t * 128]);
    float l = 0.f;
    for (int t = 0; t < ntl; t++) l += __expf(g_mt[base + t * 128] - m) * g_lt[base + t * 128];
    float inv = 1.f / l;
    for (int t = 0; t < ntl; t++) g_g[base + t * 128] = __expf(g_mt[base + t * 128] - m) * inv;
}

// ---------------- pv: ldg->reg->sts staging; g applied to A fragments ----------------
__global__ void __launch_bounds__(256, 2) pv_kernel(float* __restrict__ out) {
    extern __shared__ char smem[];
    int tid = threadIdx.x, lane = tid & 31, wid = tid >> 5, wm = wid & 3, wn = wid >> 2;
    uint32_t sb = smem_u32(smem);
    int nt = blockIdx.x * 128, qt = 15 - (int)blockIdx.y, b = blockIdx.z;
    int nch = (qt + 1) * 4;
    const __half* Pb = g_Pt + ((size_t)b * 2048 + qt * 128) * 2048;
    const __half* Vh = g_Vh + (size_t)b * 2048 * 384 + nt;
    const size_t statb = (size_t)(b * 16 + qt) * 16 * 128;
    ACC_DECL();

    uint4 rv[4];
    auto ldg = [&](int c) {
#pragma unroll
        for (int i = 0; i < 2; i++) {
            int lin = tid + 256 * i;
            int rr = lin >> 2, cc = (lin & 3) * 8;            // A: 128 x 32
            rv[i * 2 + 0] = *(const uint4*)(Pb + (size_t)rr * 2048 + c * 32 + cc);
            int r2 = lin >> 4, c2 = (lin & 15) * 8;           // B: 32 x 128
            rv[i * 2 + 1] = *(const uint4*)(Vh + (size_t)(c * 32 + r2) * 384 + c2);
        }
    };
    auto stg = [&](char* buf) {
#pragma unroll
        for (int i = 0; i < 2; i++) {
            int lin = tid + 256 * i;
            int rr = lin >> 2, cc = (lin & 3) * 8;
            *(uint4*)(buf + rr * 80 + cc * 2) = rv[i * 2 + 0];
            int r2 = lin >> 4, c2 = (lin & 15) * 8;
            *(uint4*)(buf + 10240 + r2 * 272 + c2 * 2) = rv[i * 2 + 1];
        }
    };
    uint32_t aOff = AOFF(wm, lane), bOff = BOFFT(wn, lane);
    ldg(0); stg(smem); __syncthreads();

    __half2 ga[2], gb[2];
    int rbase = wm * 32 + (lane >> 2);
    for (int c = 0; c < nch; c++) {
        if ((c & 3) == 0) {
            const float* gp = g_g + statb + (size_t)(c >> 2) * 128;
#pragma unroll
            for (int mf = 0; mf < 2; mf++) {
                ga[mf] = __float2half2_rn(gp[rbase + mf * 16]);
                gb[mf] = __float2half2_rn(gp[rbase + mf * 16 + 8]);
            }
        }
        if (c + 1 < nch) ldg(c + 1);
        chunk1t<true>(sb + (uint32_t)(c & 1) * STG_T, aOff, bOff, acc, ga, gb);
        if (c + 1 < nch) stg(smem + (size_t)((c + 1) & 1) * STG_T);
        __syncthreads();
    }

    float* Y = out + ((size_t)b * 2048 + qt * 128) * 384 + nt;
#pragma unroll
    for (int mf = 0; mf < 2; mf++)
#pragma unroll
        for (int h = 0; h < 2; h++) {
            int row = wm * 32 + mf * 16 + (lane >> 2) + h * 8;
#pragma unroll
            for (int nf = 0; nf < 8; nf++) {
                float2 v = make_float2(acc[mf][nf][h * 2], acc[mf][nf][h * 2 + 1]);
                *(float2*)&Y[(size_t)row * 384 + wn * 64 + nf * 8 + (lane & 3) * 2] = v;
            }
        }
}

extern "C" void kernel_launch(void* const* d_in, const int* in_sizes, int n_in,
                              void* d_out, int out_size) {
    const float* x  = (const float*)d_in[0];
    const float* Wq = (const float*)d_in[1];
    const float* Wk = (const float*)d_in[2];
    const float* Wv = (const float*)d_in[3];
    float* out = (float*)d_out;
    (void)in_sizes; (void)n_in; (void)out_size;

    cudaFuncSetAttribute(proj_kernel, cudaFuncAttributeMaxDynamicSharedMemorySize, SMEM_T);
    cudaFuncSetAttribute(qk_kernel,   cudaFuncAttributeMaxDynamicSharedMemorySize, SMEM_GEMM);
    cudaFuncSetAttribute(pv_kernel,   cudaFuncAttributeMaxDynamicSharedMemorySize, SMEM_T);

    cvtw_kernel<<<432, 256>>>(Wq, Wk, Wv);
    proj_kernel<<<dim3(3, 256, 3), 256, SMEM_T>>>(x);
    qk_kernel<<<dim3(136, 16), 256, SMEM_GEMM>>>();
    norm_kernel<<<256, 128>>>();
    pv_kernel<<<dim3(3, 16, 16), 256, SMEM_T>>>(out);
}

// round 11
// speedup vs baseline: 1.5032x; 1.0446x over previous
#include <cuda_runtime.h>
#include <cuda_fp16.h>
#include <cstdint>

#define SCALE 0.05103103630798288f   // 384^-0.5
#define STG_QK 20480                  // A 10240 + B 10240 (K-major)
#define STG_T  18944                  // A 10240 + B 8704  (MN-major B)
#define SMEM_QK3 (3 * STG_QK)         // 61440
#define SMEM_T3  (3 * STG_T)          // 56832
#define SMEM_PV3 (SMEM_T3 + 8192)     // + g factors [16][128] fp32

__device__ __half g_Wh[3 * 384 * 384];           // W[k][n] fp16, Wq pre-scaled
__device__ __half g_Qh[16 * 2048 * 384];
__device__ __half g_Kh[16 * 2048 * 384];
__device__ __half g_Vh[16 * 2048 * 384];
__device__ __half g_Pt[16ll * 2048 * 2048];      // P~ = exp(S - m_tile), fp16
__device__ float  g_mt[16 * 16 * 16 * 128];
__device__ float  g_lt[16 * 16 * 16 * 128];

__device__ __forceinline__ uint32_t smem_u32(const void* p) {
    uint32_t a;
    asm("{ .reg .u64 t; cvta.to.shared.u64 t, %1; cvt.u32.u64 %0, t; }" : "=r"(a) : "l"(p));
    return a;
}
__device__ __forceinline__ void ldsm4(uint32_t addr, uint32_t* r) {
    asm volatile("ldmatrix.sync.aligned.m8n8.x4.shared.b16 {%0,%1,%2,%3}, [%4];"
        : "=r"(r[0]), "=r"(r[1]), "=r"(r[2]), "=r"(r[3]) : "r"(addr));
}
__device__ __forceinline__ void ldsm4t(uint32_t addr, uint32_t* r) {
    asm volatile("ldmatrix.sync.aligned.m8n8.x4.trans.shared.b16 {%0,%1,%2,%3}, [%4];"
        : "=r"(r[0]), "=r"(r[1]), "=r"(r[2]), "=r"(r[3]) : "r"(addr));
}
__device__ __forceinline__ void mmah(float* c, const uint32_t* a, const uint32_t* b) {
    asm volatile("mma.sync.aligned.m16n8k16.row.col.f32.f16.f16.f32 "
        "{%0,%1,%2,%3}, {%4,%5,%6,%7}, {%8,%9}, {%0,%1,%2,%3};"
        : "+f"(c[0]), "+f"(c[1]), "+f"(c[2]), "+f"(c[3])
        : "r"(a[0]), "r"(a[1]), "r"(a[2]), "r"(a[3]), "r"(b[0]), "r"(b[1]));
}

#define ACC_DECL()                                   \
    float acc[2][8][4];                              \
    _Pragma("unroll") for (int i_ = 0; i_ < 2; i_++) \
    _Pragma("unroll") for (int j_ = 0; j_ < 8; j_++) \
    _Pragma("unroll") for (int q_ = 0; q_ < 4; q_++) acc[i_][j_][q_] = 0.f;

#define AOFF(wm, lane) ((uint32_t)(((wm) * 32 + ((lane) & 15)) * 80 + ((lane) >> 4) * 16))
#define BOFF(wn, lane) ((uint32_t)(((wn) * 64 + (((lane) >> 4) & 1) * 8 + ((lane) & 7)) * 80 + \
                                   (((lane) >> 3) & 1) * 16))
#define BOFFT(wn, lane) ((uint32_t)(((((lane) >> 3) & 1) * 8 + ((lane) & 7)) * 272 + \
                                    ((wn) * 64 + (((lane) >> 4) & 1) * 8) * 2))

// K-major 1-pass chunk: A@0 (80B stride), B@10240 (80B stride)
__device__ __forceinline__ void chunk1(uint32_t sbase, uint32_t aOff, uint32_t bOff,
                                       float acc[2][8][4]) {
#pragma unroll
    for (int ks = 0; ks < 2; ks++) {
        uint32_t a[2][4], b[8][2];
#pragma unroll
        for (int mf = 0; mf < 2; mf++) ldsm4(sbase + aOff + mf * 1280 + ks * 32, a[mf]);
#pragma unroll
        for (int n2 = 0; n2 < 4; n2++) {
            uint32_t r[4];
            ldsm4(sbase + 10240 + bOff + n2 * 1280 + ks * 32, r);
            b[n2 * 2][0] = r[0]; b[n2 * 2][1] = r[1];
            b[n2 * 2 + 1][0] = r[2]; b[n2 * 2 + 1][1] = r[3];
        }
#pragma unroll
        for (int mf = 0; mf < 2; mf++)
#pragma unroll
            for (int nf = 0; nf < 8; nf++) mmah(acc[mf][nf], a[mf], b[nf]);
    }
}

// MN-major-B 1-pass chunk: A@0, B@10240 (32 rows x 272B), ldsm.trans.
// If SCALED, multiply A fragments by per-row g factors (ga=rows r, gb=rows r+8).
template <bool SCALED>
__device__ __forceinline__ void chunk1t(uint32_t sbase, uint32_t aOff, uint32_t bOff,
                                        float acc[2][8][4],
                                        const __half2* ga, const __half2* gb) {
#pragma unroll
    for (int ks = 0; ks < 2; ks++) {
        uint32_t a[2][4], b[8][2];
#pragma unroll
        for (int mf = 0; mf < 2; mf++) {
            ldsm4(sbase + aOff + mf * 1280 + ks * 32, a[mf]);
            if (SCALED) {
                __half2* ap = reinterpret_cast<__half2*>(a[mf]);
                ap[0] = __hmul2(ap[0], ga[mf]);
                ap[2] = __hmul2(ap[2], ga[mf]);
                ap[1] = __hmul2(ap[1], gb[mf]);
                ap[3] = __hmul2(ap[3], gb[mf]);
            }
        }
#pragma unroll
        for (int n2 = 0; n2 < 4; n2++) {
            uint32_t r[4];
            ldsm4t(sbase + 10240 + bOff + (uint32_t)(ks * 16 * 272 + n2 * 32), r);
            b[n2 * 2][0] = r[0]; b[n2 * 2][1] = r[1];
            b[n2 * 2 + 1][0] = r[2]; b[n2 * 2 + 1][1] = r[3];
        }
#pragma unroll
        for (int mf = 0; mf < 2; mf++)
#pragma unroll
            for (int nf = 0; nf < 8; nf++) mmah(acc[mf][nf], a[mf], b[nf]);
    }
}

struct __align__(8) hpair { __half2 a, b; };
__device__ __forceinline__ hpair to_h(float4 v) {
    hpair r; r.a = __floats2half2_rn(v.x, v.y); r.b = __floats2half2_rn(v.z, v.w); return r;
}

// ---------------- cvtw: W fp32 -> fp16 (SCALE folded into Wq) ----------------
__global__ void cvtw_kernel(const float* __restrict__ Wq, const float* __restrict__ Wk,
                            const float* __restrict__ Wv) {
    int i = (blockIdx.x * 256 + threadIdx.x) * 4;
    int z = i / 147456, r = i - z * 147456;
    const float* W = (z == 0) ? Wq : ((z == 1) ? Wk : Wv);
    float4 v = *(const float4*)(W + r);
    float s = (z == 0) ? SCALE : 1.f;
    v.x *= s; v.y *= s; v.z *= s; v.w *= s;
    *(hpair*)&g_Wh[i] = to_h(v);
}

// ---------------- proj: X fp32 (convert in stage) x W fp16, 3-stage pipeline ----------------
__global__ void __launch_bounds__(256, 2) proj_kernel(const float* __restrict__ X) {
    extern __shared__ char smem[];
    int tid = threadIdx.x, lane = tid & 31, wid = tid >> 5, wm = wid & 3, wn = wid >> 2;
    uint32_t sb = smem_u32(smem);
    int nt = blockIdx.x * 128, mt = blockIdx.y * 128, z = blockIdx.z;
    const float*  gA = X + (size_t)mt * 384;
    const __half* gW = g_Wh + (size_t)z * 147456 + nt;
    ACC_DECL();

    float4 va[4]; uint4 wb[2];
    auto ldg = [&](int c) {
#pragma unroll
        for (int i = 0; i < 4; i++) {
            int lin = tid + 256 * i, row = lin >> 3, c4 = (lin & 7) * 4;
            va[i] = *(const float4*)(gA + (size_t)row * 384 + c * 32 + c4);
        }
#pragma unroll
        for (int i = 0; i < 2; i++) {
            int lin = tid + 256 * i, r2 = lin >> 4, c2 = (lin & 15) * 8;
            wb[i] = *(const uint4*)(gW + (size_t)(c * 32 + r2) * 384 + c2);
        }
    };
    auto stg = [&](char* buf) {
#pragma unroll
        for (int i = 0; i < 4; i++) {
            int lin = tid + 256 * i, row = lin >> 3, c4 = (lin & 7) * 4;
            *(hpair*)(buf + row * 80 + c4 * 2) = to_h(va[i]);
        }
#pragma unroll
        for (int i = 0; i < 2; i++) {
            int lin = tid + 256 * i, r2 = lin >> 4, c2 = (lin & 15) * 8;
            *(uint4*)(buf + 10240 + r2 * 272 + c2 * 2) = wb[i];
        }
    };
    uint32_t aOff = AOFF(wm, lane), bOff = BOFFT(wn, lane);
    ldg(0); stg(smem); ldg(1);
    __syncthreads();
    int rs = 0;
    for (int c = 0; c < 12; c++) {
        int ws = (rs == 2) ? 0 : rs + 1;
        if (c + 1 < 12) stg(smem + ws * STG_T);
        if (c + 2 < 12) ldg(c + 2);
        chunk1t<false>(sb + (uint32_t)(rs * STG_T), aOff, bOff, acc, 0, 0);
        __syncthreads();
        rs = ws;
    }

    __half* Yh = (z == 0) ? g_Qh : ((z == 1) ? g_Kh : g_Vh);
#pragma unroll
    for (int mf = 0; mf < 2; mf++)
#pragma unroll
        for (int h = 0; h < 2; h++) {
            int row = mt + wm * 32 + mf * 16 + (lane >> 2) + h * 8;
#pragma unroll
            for (int nf = 0; nf < 8; nf++) {
                int col = nt + wn * 64 + nf * 8 + (lane & 3) * 2;
                *(__half2*)&Yh[(size_t)row * 384 + col] =
                    __floats2half2_rn(acc[mf][nf][h * 2], acc[mf][nf][h * 2 + 1]);
            }
        }
}

// ---------------- qk: 3-stage pipeline + fused local softmax ----------------
__global__ void __launch_bounds__(256, 2) qk_kernel() {
    extern __shared__ char smem[];
    int tid = threadIdx.x, lane = tid & 31, wid = tid >> 5, wm = wid & 3, wn = wid >> 2;
    uint32_t sb = smem_u32(smem);
    int b = blockIdx.y, r_ = blockIdx.x, qt = 0;
    while (r_ > qt) { r_ -= qt + 1; qt++; }
    int kt = r_;
    size_t qb = ((size_t)b * 2048 + qt * 128) * 384;
    size_t kb = ((size_t)b * 2048 + kt * 128) * 384;
    ACC_DECL();

    uint4 rv[4];
    auto ldg = [&](int c) {
#pragma unroll
        for (int i = 0; i < 2; i++) {
            int lin = tid + 256 * i, rr = lin >> 2, cc = (lin & 3) * 8;
            size_t o = (size_t)rr * 384 + c * 32 + cc;
            rv[i * 2 + 0] = *(const uint4*)(g_Qh + qb + o);
            rv[i * 2 + 1] = *(const uint4*)(g_Kh + kb + o);
        }
    };
    auto stg = [&](char* buf) {
#pragma unroll
        for (int i = 0; i < 2; i++) {
            int lin = tid + 256 * i, rr = lin >> 2, cc = (lin & 3) * 8;
            int o = rr * 80 + cc * 2;
            *(uint4*)(buf + o)         = rv[i * 2 + 0];
            *(uint4*)(buf + 10240 + o) = rv[i * 2 + 1];
        }
    };
    uint32_t aOff = AOFF(wm, lane), bOff = BOFF(wn, lane);
    ldg(0); stg(smem); ldg(1);
    __syncthreads();
    int rs = 0;
    for (int c = 0; c < 12; c++) {
        int ws = (rs == 2) ? 0 : rs + 1;
        if (c + 1 < 12) stg(smem + ws * STG_QK);
        if (c + 2 < 12) ldg(c + 2);
        chunk1(sb + (uint32_t)(rs * STG_QK), aOff, bOff, acc);
        __syncthreads();
        rs = ws;
    }

    // ---- fused epilogue: mask, local max, exp, row sums, P~ store ----
    float* sR = (float*)smem;
    float pm[2][2] = {{-1e30f, -1e30f}, {-1e30f, -1e30f}};
#pragma unroll
    for (int mf = 0; mf < 2; mf++)
#pragma unroll
        for (int nf = 0; nf < 8; nf++)
#pragma unroll
            for (int q = 0; q < 4; q++) {
                int h = q >> 1;
                int qg = qt * 128 + wm * 32 + mf * 16 + (lane >> 2) + h * 8;
                int kg = kt * 128 + wn * 64 + nf * 8 + (lane & 3) * 2 + (q & 1);
                if (kg > qg) acc[mf][nf][q] = -1e30f;
                pm[mf][h] = fmaxf(pm[mf][h], acc[mf][nf][q]);
            }
#pragma unroll
    for (int mf = 0; mf < 2; mf++)
#pragma unroll
        for (int h = 0; h < 2; h++) {
            pm[mf][h] = fmaxf(pm[mf][h], __shfl_xor_sync(~0u, pm[mf][h], 1));
            pm[mf][h] = fmaxf(pm[mf][h], __shfl_xor_sync(~0u, pm[mf][h], 2));
        }
    int rl[2][2];
#pragma unroll
    for (int mf = 0; mf < 2; mf++)
#pragma unroll
        for (int h = 0; h < 2; h++)
            rl[mf][h] = wm * 32 + mf * 16 + (lane >> 2) + h * 8;
    if ((lane & 3) == 0)
#pragma unroll
        for (int mf = 0; mf < 2; mf++)
#pragma unroll
            for (int h = 0; h < 2; h++) sR[wn * 128 + rl[mf][h]] = pm[mf][h];
    __syncthreads();
    float mrow[2][2], ps[2][2] = {{0.f, 0.f}, {0.f, 0.f}};
#pragma unroll
    for (int mf = 0; mf < 2; mf++)
#pragma unroll
        for (int h = 0; h < 2; h++) mrow[mf][h] = fmaxf(sR[rl[mf][h]], sR[128 + rl[mf][h]]);
#pragma unroll
    for (int mf = 0; mf < 2; mf++)
#pragma unroll
        for (int nf = 0; nf < 8; nf++)
#pragma unroll
            for (int q = 0; q < 4; q++) {
                int h = q >> 1;
                float p = __expf(acc[mf][nf][q] - mrow[mf][h]);
                acc[mf][nf][q] = p;
                ps[mf][h] += p;
            }
#pragma unroll
    for (int mf = 0; mf < 2; mf++)
#pragma unroll
        for (int h = 0; h < 2; h++) {
            ps[mf][h] += __shfl_xor_sync(~0u, ps[mf][h], 1);
            ps[mf][h] += __shfl_xor_sync(~0u, ps[mf][h], 2);
        }
    __syncthreads();
    if ((lane & 3) == 0)
#pragma unroll
        for (int mf = 0; mf < 2; mf++)
#pragma unroll
            for (int h = 0; h < 2; h++) sR[wn * 128 + rl[mf][h]] = ps[mf][h];
    __syncthreads();
    size_t statb = ((size_t)(b * 16 + qt) * 16 + kt) * 128;
    if (wn == 0 && (lane & 3) == 0)
#pragma unroll
        for (int mf = 0; mf < 2; mf++)
#pragma unroll
            for (int h = 0; h < 2; h++) {
                g_mt[statb + rl[mf][h]] = mrow[mf][h];
                g_lt[statb + rl[mf][h]] = sR[rl[mf][h]] + sR[128 + rl[mf][h]];
            }
    __half* Prow = g_Pt + ((size_t)b * 2048 + qt * 128) * 2048 + (size_t)kt * 128;
#pragma unroll
    for (int mf = 0; mf < 2; mf++)
#pragma unroll
        for (int h = 0; h < 2; h++) {
#pragma unroll
            for (int nf = 0; nf < 8; nf++) {
                int col = wn * 64 + nf * 8 + (lane & 3) * 2;
                *(__half2*)&Prow[(size_t)rl[mf][h] * 2048 + col] =
                    __floats2half2_rn(acc[mf][nf][h * 2], acc[mf][nf][h * 2 + 1]);
            }
        }
}

// ---------------- pv: 3-stage pipeline; norm fused; g applied to A fragments ----------------
__global__ void __launch_bounds__(256, 2) pv_kernel(float* __restrict__ out) {
    extern __shared__ char smem[];
    int tid = threadIdx.x, lane = tid & 31, wid = tid >> 5, wm = wid & 3, wn = wid >> 2;
    uint32_t sb = smem_u32(smem);
    int nt = blockIdx.x * 128, qt = 15 - (int)blockIdx.y, b = blockIdx.z;
    int nch = (qt + 1) * 4;
    const __half* Pb = g_Pt + ((size_t)b * 2048 + qt * 128) * 2048;
    const __half* Vh = g_Vh + (size_t)b * 2048 * 384 + nt;
    const size_t statb = (size_t)(b * 16 + qt) * 16 * 128;
    float* sg = (float*)(smem + SMEM_T3);
    ACC_DECL();

    // fused norm: per-row fold factors into smem (covered by prologue sync)
    if (tid < 128) {
        int ntl = qt + 1;
        size_t base = statb + tid;
        float m = -1e30f;
        for (int t = 0; t < ntl; t++) m = fmaxf(m, g_mt[base + t * 128]);
        float l = 0.f;
        for (int t = 0; t < ntl; t++) l += __expf(g_mt[base + t * 128] - m) * g_lt[base + t * 128];
        float inv = 1.f / l;
        for (int t = 0; t < ntl; t++) sg[t * 128 + tid] = __expf(g_mt[base + t * 128] - m) * inv;
    }

    uint4 rv[4];
    auto ldg = [&](int c) {
#pragma unroll
        for (int i = 0; i < 2; i++) {
            int lin = tid + 256 * i;
            int rr = lin >> 2, cc = (lin & 3) * 8;            // A: 128 x 32
            rv[i * 2 + 0] = *(const uint4*)(Pb + (size_t)rr * 2048 + c * 32 + cc);
            int r2 = lin >> 4, c2 = (lin & 15) * 8;           // B: 32 x 128
            rv[i * 2 + 1] = *(const uint4*)(Vh + (size_t)(c * 32 + r2) * 384 + c2);
        }
    };
    auto stg = [&](char* buf) {
#pragma unroll
        for (int i = 0; i < 2; i++) {
            int lin = tid + 256 * i;
            int rr = lin >> 2, cc = (lin & 3) * 8;
            *(uint4*)(buf + rr * 80 + cc * 2) = rv[i * 2 + 0];
            int r2 = lin >> 4, c2 = (lin & 15) * 8;
            *(uint4*)(buf + 10240 + r2 * 272 + c2 * 2) = rv[i * 2 + 1];
        }
    };
    uint32_t aOff = AOFF(wm, lane), bOff = BOFFT(wn, lane);
    ldg(0); stg(smem); ldg(1);
    __syncthreads();

    __half2 ga[2], gb[2];
    int rbase = wm * 32 + (lane >> 2);
    int rs = 0;
    for (int c = 0; c < nch; c++) {
        if ((c & 3) == 0) {
            const float* gp = sg + (c >> 2) * 128;
#pragma unroll
            for (int mf = 0; mf < 2; mf++) {
                ga[mf] = __float2half2_rn(gp[rbase + mf * 16]);
                gb[mf] = __float2half2_rn(gp[rbase + mf * 16 + 8]);
            }
        }
        int ws = (rs == 2) ? 0 : rs + 1;
        if (c + 1 < nch) stg(smem + ws * STG_T);
        if (c + 2 < nch) ldg(c + 2);
        chunk1t<true>(sb + (uint32_t)(rs * STG_T), aOff, bOff, acc, ga, gb);
        __syncthreads();
        rs = ws;
    }

    float* Y = out + ((size_t)b * 2048 + qt * 128) * 384 + nt;
#pragma unroll
    for (int mf = 0; mf < 2; mf++)
#pragma unroll
        for (int h = 0; h < 2; h++) {
            int row = wm * 32 + mf * 16 + (lane >> 2) + h * 8;
#pragma unroll
            for (int nf = 0; nf < 8; nf++) {
                float2 v = make_float2(acc[mf][nf][h * 2], acc[mf][nf][h * 2 + 1]);
                *(float2*)&Y[(size_t)row * 384 + wn * 64 + nf * 8 + (lane & 3) * 2] = v;
            }
        }
}

extern "C" void kernel_launch(void* const* d_in, const int* in_sizes, int n_in,
                              void* d_out, int out_size) {
    const float* x  = (const float*)d_in[0];
    const float* Wq = (const float*)d_in[1];
    const float* Wk = (const float*)d_in[2];
    const float* Wv = (const float*)d_in[3];
    float* out = (float*)d_out;
    (void)in_sizes; (void)n_in; (void)out_size;

    cudaFuncSetAttribute(proj_kernel, cudaFuncAttributeMaxDynamicSharedMemorySize, SMEM_T3);
    cudaFuncSetAttribute(qk_kernel,   cudaFuncAttributeMaxDynamicSharedMemorySize, SMEM_QK3);
    cudaFuncSetAttribute(pv_kernel,   cudaFuncAttributeMaxDynamicSharedMemorySize, SMEM_PV3);

    cvtw_kernel<<<432, 256>>>(Wq, Wk, Wv);
    proj_kernel<<<dim3(3, 256, 3), 256, SMEM_T3>>>(x);
    qk_kernel<<<dim3(136, 16), 256, SMEM_QK3>>>();
    pv_kernel<<<dim3(3, 16, 16), 256, SMEM_PV3>>>(out);
}